// round 4
// baseline (speedup 1.0000x reference)
#include <cuda_runtime.h>

#define TPB 256
#define APT 2                 // anchors per thread
#define CHUNK (TPB * APT)     // anchors per block = 512
#define NW   (TPB / 32)       // warps per block = 8
#define MAXN 128              // max gt boxes per image supported

// Scratch (device globals; no allocation allowed)
__device__ unsigned long long g_partial[1 << 19];  // per-(b,n) per-chunk best keys
__device__ unsigned long long g_abest[1 << 20];    // per-(b,a) packed (iou, box idx)
__device__ int                g_winner[1 << 20];   // per-(b,a) segment_max winner
__device__ float              g_miou[8192];        // per-(b,n) max iou over anchors

__device__ __forceinline__ float iou_fn(float ax1, float ay1, float ax2, float ay2,
                                        float areaA, float4 bb, float sa)
{
    float ltx = fmaxf(ax1, bb.x), lty = fmaxf(ay1, bb.y);
    float rbx = fminf(ax2, bb.z), rby = fminf(ay2, bb.w);
    float w = fmaxf(rbx - ltx, 0.f), h = fmaxf(rby - lty, 0.f);
    float inter = w * h;
    return __fdividef(inter, areaA + sa - inter);
}

// Per-box warp argmax over anchors: max IoU (uint-monotone, IoU>=0),
// tie -> min anchor index. Lane 0 stores packed key.
__device__ __forceinline__ void warp_box_reduce(
    float mi, unsigned wa, int n, int lane, int wid, unsigned long long* swb)
{
    unsigned u = __float_as_uint(mi);
    unsigned m = __reduce_max_sync(0xffffffffu, u);
    unsigned cand = (u == m) ? wa : 0xFFFFFFFFu;
    unsigned amin = __reduce_min_sync(0xffffffffu, cand);
    if (lane == 0)
        swb[n * NW + wid] = ((unsigned long long)m << 32) | (0xFFFFFFFFu - amin);
}

// K1: for each (batch, 512-anchor chunk): compute all IoUs vs N boxes once.
__global__ void __launch_bounds__(TPB)
k_phase1(const float4* __restrict__ anchors, const float4* __restrict__ bboxes,
         int A, int N, int numChunks)
{
    __shared__ float4 sbox[MAXN];
    __shared__ float  sarea[MAXN];
    __shared__ unsigned long long swb[MAXN * NW];

    const int b = blockIdx.y, chunk = blockIdx.x, tid = threadIdx.x;
    const int lane = tid & 31, wid = tid >> 5;

    for (int n = tid; n < N; n += TPB) {
        float4 bb = bboxes[b * N + n];
        sbox[n] = bb;
        sarea[n] = (bb.z - bb.x) * (bb.w - bb.y);
    }
    __syncthreads();

    const int a0 = chunk * CHUNK + tid;
    const int a1 = a0 + TPB;
    const bool v0 = (a0 < A), v1 = (a1 < A);

    float ax1a = 0.f, ay1a = 0.f, ax2a = 0.f, ay2a = 0.f, areaA0 = 0.f;
    float ax1b = 0.f, ay1b = 0.f, ax2b = 0.f, ay2b = 0.f, areaA1 = 0.f;
    if (v0) {
        float4 c = anchors[a0];
        ax1a = c.x - c.z * 0.5f;  ay1a = c.y - c.w * 0.5f;
        ax2a = c.x + c.z * 0.5f;  ay2a = c.y + c.w * 0.5f;
        areaA0 = (ax2a - ax1a) * (ay2a - ay1a);      // reference order
        g_winner[(size_t)b * A + a0] = -1;
    }
    if (v1) {
        float4 c = anchors[a1];
        ax1b = c.x - c.z * 0.5f;  ay1b = c.y - c.w * 0.5f;
        ax2b = c.x + c.z * 0.5f;  ay2b = c.y + c.w * 0.5f;
        areaA1 = (ax2b - ax1b) * (ay2b - ay1b);
        g_winner[(size_t)b * A + a1] = -1;
    }
    // dummy anchors (v==false) have zero extent -> IoU exactly 0 vs any valid
    // box; their index is larger than every real anchor so they can never win
    // a tie at iou 0 against a real anchor... except when ALL anchors in the
    // warp give 0. Guard: force dummy's merged contribution to lose ties by
    // index ordering (a1 > a0 >= A-safe). For A % CHUNK == 0 (A=65536) all valid.

    float bestI0 = 0.0f, bestI1 = 0.0f;   // IoU >= 0 always; argmax(all 0)=0
    int   bestN0 = 0,    bestN1 = 0;

    int n = 0;
    for (; n + 2 <= N; n += 2) {
        float4 bbA = sbox[n];     float saA = sarea[n];
        float4 bbB = sbox[n + 1]; float saB = sarea[n + 1];

        float i0A = iou_fn(ax1a, ay1a, ax2a, ay2a, areaA0, bbA, saA);
        float i1A = iou_fn(ax1b, ay1b, ax2b, ay2b, areaA1, bbA, saA);
        float i0B = iou_fn(ax1a, ay1a, ax2a, ay2a, areaA0, bbB, saB);
        float i1B = iou_fn(ax1b, ay1b, ax2b, ay2b, areaA1, bbB, saB);

        if (i0A > bestI0) { bestI0 = i0A; bestN0 = n; }
        if (i1A > bestI1) { bestI1 = i1A; bestN1 = n; }
        if (i0B > bestI0) { bestI0 = i0B; bestN0 = n + 1; }
        if (i1B > bestI1) { bestI1 = i1B; bestN1 = n + 1; }

        // merge two anchors (strict > keeps lower anchor index = a0)
        float miA = (i1A > i0A) ? i1A : i0A;
        unsigned waA = (i1A > i0A) ? (unsigned)a1 : (unsigned)a0;
        float miB = (i1B > i0B) ? i1B : i0B;
        unsigned waB = (i1B > i0B) ? (unsigned)a1 : (unsigned)a0;

        warp_box_reduce(miA, waA, n,     lane, wid, swb);
        warp_box_reduce(miB, waB, n + 1, lane, wid, swb);
    }
    for (; n < N; n++) {
        float4 bb = sbox[n]; float sa = sarea[n];
        float i0 = iou_fn(ax1a, ay1a, ax2a, ay2a, areaA0, bb, sa);
        float i1 = iou_fn(ax1b, ay1b, ax2b, ay2b, areaA1, bb, sa);
        if (i0 > bestI0) { bestI0 = i0; bestN0 = n; }
        if (i1 > bestI1) { bestI1 = i1; bestN1 = n; }
        float mi = (i1 > i0) ? i1 : i0;
        unsigned wa = (i1 > i0) ? (unsigned)a1 : (unsigned)a0;
        warp_box_reduce(mi, wa, n, lane, wid, swb);
    }

    if (v0)
        g_abest[(size_t)b * A + a0] =
            ((unsigned long long)__float_as_uint(bestI0) << 32) | (unsigned)bestN0;
    if (v1)
        g_abest[(size_t)b * A + a1] =
            ((unsigned long long)__float_as_uint(bestI1) << 32) | (unsigned)bestN1;

    __syncthreads();
    for (int nn = tid; nn < N; nn += TPB) {
        unsigned long long best = swb[nn * NW];
        #pragma unroll
        for (int w8 = 1; w8 < NW; w8++)
            if (swb[nn * NW + w8] > best) best = swb[nn * NW + w8];
        g_partial[((size_t)(b * N + nn)) * numChunks + chunk] = best;
    }
}

// K2: reduce chunk partials per (b,n) -> max_iou_of_bbox + anchor argmax,
//     then segment_max scatter: winner[anchor] = max n claiming it.
__global__ void __launch_bounds__(256)
k_phase2(int A, int N, int numChunks)
{
    const int bn = blockIdx.x, tid = threadIdx.x;
    const int lane = tid & 31, wid = tid >> 5;
    const unsigned long long* p = g_partial + (size_t)bn * numChunks;

    unsigned long long key = 0;
    for (int c = tid; c < numChunks; c += 256) {
        unsigned long long v = p[c];
        if (v > key) key = v;
    }
    __shared__ unsigned long long sred[8];
    #pragma unroll
    for (int off = 16; off; off >>= 1) {
        unsigned long long o = __shfl_down_sync(0xffffffffu, key, off);
        if (o > key) key = o;
    }
    if (lane == 0) sred[wid] = key;
    __syncthreads();
    if (wid == 0) {
        key = (lane < 8) ? sred[lane] : 0ull;
        #pragma unroll
        for (int off = 4; off; off >>= 1) {
            unsigned long long o = __shfl_down_sync(0xffffffffu, key, off);
            if (o > key) key = o;
        }
        if (lane == 0) {
            float miou = __uint_as_float((unsigned)(key >> 32));
            int   idx  = (int)(0xFFFFFFFFu - (unsigned)key);
            g_miou[bn] = miou;
            int b = bn / N, n = bn - b * N;
            atomicMax(&g_winner[(size_t)b * A + idx], n);
        }
    }
}

// K3: epilogue per anchor: winner override, scores, conf scatter, delta encode.
__global__ void __launch_bounds__(256)
k_phase3(const float4* __restrict__ anchors, const float4* __restrict__ bboxes,
         const int* __restrict__ labels,
         const float* __restrict__ enc_mean, const float* __restrict__ enc_std,
         const float* __restrict__ thr_ptr,
         float* __restrict__ out_conf, float4* __restrict__ out_delta,
         int A, int N, int C)
{
    __shared__ float4 sbox[MAXN];
    __shared__ int    slab[MAXN];
    __shared__ float  smiou[MAXN];

    const int b = blockIdx.y, tid = threadIdx.x;
    for (int n = tid; n < N; n += 256) {
        sbox[n]  = bboxes[b * N + n];
        slab[n]  = labels[b * N + n];
        smiou[n] = g_miou[b * N + n];
    }
    __syncthreads();

    const int a = blockIdx.x * 256 + tid;
    if (a >= A) return;

    const float thr = __ldg(thr_ptr);
    unsigned long long ab = g_abest[(size_t)b * A + a];
    float miou = __uint_as_float((unsigned)(ab >> 32));
    int   idx  = (int)(unsigned)ab;

    int w = g_winner[(size_t)b * A + a];
    if (w >= 0) { idx = w; miou = smiou[w]; }

    float den = fmaxf(smiou[idx], thr);
    if (miou < thr * 0.5f) miou = 0.f;
    float score = miou / den;

    int lab = slab[idx];
    if (lab <= 0) { score = 0.f; lab = 0; }

    const size_t base = (size_t)b * A + a;
    for (int c = 0; c < C; c++)
        out_conf[base * C + c] = (lab == c + 1) ? score : 0.f;

    float4 m   = sbox[idx];
    float4 anc = anchors[a];
    float mcx = (m.x + m.z) * 0.5f, mcy = (m.y + m.w) * 0.5f;
    float mw  = m.z - m.x,          mh  = m.w - m.y;
    float d0 = (mcx - anc.x) / anc.z;
    float d1 = (mcy - anc.y) / anc.w;
    float d2 = logf(mw / anc.z);
    float d3 = logf(mh / anc.w);
    float4 dv;
    dv.x = (d0 - __ldg(&enc_mean[0])) / __ldg(&enc_std[0]);
    dv.y = (d1 - __ldg(&enc_mean[1])) / __ldg(&enc_std[1]);
    dv.z = (d2 - __ldg(&enc_mean[2])) / __ldg(&enc_std[2]);
    dv.w = (d3 - __ldg(&enc_mean[3])) / __ldg(&enc_std[3]);
    out_delta[base] = dv;
}

extern "C" void kernel_launch(void* const* d_in, const int* in_sizes, int n_in,
                              void* d_out, int out_size)
{
    const float* anchors = (const float*)d_in[0];
    const int*   labels  = (const int*)d_in[1];
    const float* bboxes  = (const float*)d_in[2];
    const float* emean   = (const float*)d_in[3];
    const float* estd    = (const float*)d_in[4];
    const float* thr     = (const float*)d_in[5];

    const int A  = in_sizes[0] / 4;          // anchors [A,4]
    const int BN = in_sizes[1];              // labels [B,N]
    int B = out_size / (5 * A);
    if (B <= 0) B = 1;
    const int N = BN / B;
    const int C = (int)((long)out_size / ((long)B * A)) - 4;

    const int numChunks = (A + CHUNK - 1) / CHUNK;
    dim3 grid1(numChunks, B);

    k_phase1<<<grid1, TPB>>>((const float4*)anchors, (const float4*)bboxes, A, N, numChunks);
    k_phase2<<<B * N, 256>>>(A, N, numChunks);

    float*  out_conf  = (float*)d_out;
    float4* out_delta = (float4*)((float*)d_out + (size_t)B * A * C);
    dim3 grid3((A + 255) / 256, B);
    k_phase3<<<grid3, 256>>>((const float4*)anchors, (const float4*)bboxes, labels,
                             emean, estd, thr, out_conf, out_delta, A, N, C);
}